// round 16
// baseline (speedup 1.0000x reference)
#include <cuda_runtime.h>
#include <cuda_bf16.h>
#include <math.h>
#include <stdint.h>

// Problem constants
#define BB 16
#define TT 2000
#define CC 1536
#define NH 8
#define DD 192
#define QQ 256
#define AA 192

// ===================== warp-MMA helpers (sm_80+ baseline) ==================
__device__ __forceinline__ uint32_t smem_u32(const void* p) {
    uint32_t a;
    asm("{ .reg .u64 t; cvta.to.shared.u64 t, %1; cvt.u32.u64 %0, t; }"
        : "=r"(a) : "l"(p));
    return a;
}
__device__ __forceinline__ void ldsm_x4(uint32_t r[4], uint32_t addr) {
    asm volatile("ldmatrix.sync.aligned.m8n8.x4.shared.b16 {%0,%1,%2,%3}, [%4];"
                 : "=r"(r[0]), "=r"(r[1]), "=r"(r[2]), "=r"(r[3]) : "r"(addr));
}
__device__ __forceinline__ void mma_bf16(float c[4], const uint32_t a[4],
                                         uint32_t b0, uint32_t b1) {
    asm volatile("mma.sync.aligned.m16n8k16.row.col.f32.bf16.bf16.f32 "
                 "{%0,%1,%2,%3}, {%4,%5,%6,%7}, {%8,%9}, {%0,%1,%2,%3};"
                 : "+f"(c[0]), "+f"(c[1]), "+f"(c[2]), "+f"(c[3])
                 : "r"(a[0]), "r"(a[1]), "r"(a[2]), "r"(a[3]), "r"(b0), "r"(b1));
}
__device__ __forceinline__ uint32_t pack_bf(float lo, float hi) {
    uint32_t r;
    asm("cvt.rn.bf16x2.f32 %0, %1, %2;" : "=r"(r) : "f"(hi), "f"(lo));
    return r;
}
__device__ __forceinline__ float bflo(uint32_t u) { return __uint_as_float(u << 16); }
__device__ __forceinline__ float bfhi(uint32_t u) { return __uint_as_float(u & 0xffff0000u); }
__device__ __forceinline__ float tanha(float x) {
    float r; asm("tanh.approx.f32 %0, %1;" : "=f"(r) : "f"(x)); return r;
}
#define CP_ASYNC16(dst, src) \
    asm volatile("cp.async.cg.shared.global [%0], [%1], 16;" :: "r"(dst), "l"(src))
#define CP_COMMIT() asm volatile("cp.async.commit_group;" ::: "memory")
#define CP_WAITG(n) asm volatile("cp.async.wait_group %0;" :: "n"(n) : "memory")

// ---------------- scratch (device globals: no allocations allowed) --------
__device__ float g_c[BB * CC * 2];
__device__ float g_hck[BB * NH * QQ];
__device__ float g_t1[BB * NH * QQ];
__device__ float g_cq2[BB * NH * AA];
__device__ float g_vcqsum[NH * AA];
__device__ float g_ckdotp[BB * NH * 8];
__device__ float g_vcqdotp[BB * NH * 6];
__device__ float g_qdotp[NH * 8];
__device__ __nv_bfloat16 g_w1t[NH * QQ * DD];               // W1^T [n][q][d] bf16
__device__ __nv_bfloat16 g_qTb[NH * AA * QQ];               // query^T/sqrt(Q) bf16
__device__ float4 g_pp[BB * NH * 16 * AA];                  // pool partials per tile

// ---------------- K-front: stats + prepw + prepq + qdot (one launch) -------
__global__ __launch_bounds__(256) void k_front(
        const float* __restrict__ ht, const float* __restrict__ W1,
        const float* __restrict__ query, const float* __restrict__ vhq,
        const float* __restrict__ vcq) {
    __shared__ float shbuf[1088];
    int bid = blockIdx.x;
    int tid = threadIdx.x;

    if (bid < 384) {
        int b = bid / 24, cht = bid % 24;
        int c = tid & 63, sl = tid >> 6;
        int ch = cht * 64 + c;
        float s = 0.f, s2 = 0.f;
        const float* p = ht + (size_t)b * TT * CC + ch;
        for (int t = sl; t < TT; t += 4) {
            float v = p[(size_t)t * CC];
            s += v; s2 += v * v;
        }
        shbuf[sl * 64 + c] = s;
        shbuf[256 + sl * 64 + c] = s2;
        __syncthreads();
        if (sl == 0) {
            for (int j = 1; j < 4; j++) { s += shbuf[j * 64 + c]; s2 += shbuf[256 + j * 64 + c]; }
            float mean = s * (1.f / TT);
            float var = (s2 - (float)TT * mean * mean) * (1.f / (TT - 1));
            float sd = sqrtf(fmaxf(var, 0.f));
            g_c[((size_t)b * CC + ch) * 2 + 0] = mean;
            g_c[((size_t)b * CC + ch) * 2 + 1] = sd;
        }
    } else if (bid < 768) {
        int idx = bid - 384;
        int tile = idx % 48, n = idx / 48;
        int d0 = (tile % 6) * 32, q0 = (tile / 6) * 32;
        int tx = tid & 31, ty = tid >> 5;
#pragma unroll
        for (int j = 0; j < 4; j++)
            shbuf[(ty + j * 8) * 33 + tx] = W1[((size_t)n * DD + d0 + ty + j * 8) * QQ + q0 + tx];
        __syncthreads();
#pragma unroll
        for (int j = 0; j < 4; j++)
            g_w1t[((size_t)n * QQ + q0 + ty + j * 8) * DD + d0 + tx] =
                __float2bfloat16_rn(shbuf[tx * 33 + ty + j * 8]);
    } else if (bid < 1152) {
        int idx = bid - 768;
        int tile = idx % 48, n = idx / 48;
        int a0 = (tile % 6) * 32, q0 = (tile / 6) * 32;
        int tx = tid & 31, ty = tid >> 5;
#pragma unroll
        for (int j = 0; j < 4; j++)
            shbuf[(ty + j * 8) * 33 + tx] = query[((size_t)n * QQ + q0 + ty + j * 8) * AA + a0 + tx];
        __syncthreads();
#pragma unroll
        for (int j = 0; j < 4; j++)
            g_qTb[((size_t)n * AA + a0 + ty + j * 8) * QQ + q0 + tx] =
                __float2bfloat16_rn(shbuf[tx * 33 + ty + j * 8] * (1.f / 16.f));
    } else {
        int idx = bid - 1152;
        int s = idx % 8, n = idx / 8;
        float acc = 0.f;
        int base = s * (AA * QQ / 8);
        for (int ii = tid; ii < AA * QQ / 8; ii += 256) {
            int i = base + ii;
            int a = i >> 8, q = i & 255;
            acc += query[(n * QQ + q) * AA + a] * vhq[n * AA * QQ + i];
        }
        shbuf[tid] = acc;
        __syncthreads();
        for (int off = 128; off > 0; off >>= 1) {
            if (tid < off) shbuf[tid] += shbuf[tid + off];
            __syncthreads();
        }
        if (tid == 0) g_qdotp[n * 8 + s] = shbuf[0];

        int w = tid >> 5, lane = tid & 31;
        for (int r = w; r < AA / 8; r += 8) {
            int a = s * (AA / 8) + r;
            const float* vp = vcq + ((size_t)n * AA + a) * QQ;
            float sum = 0.f;
            for (int q = lane; q < QQ; q += 32) sum += vp[q];
#pragma unroll
            for (int o = 16; o > 0; o >>= 1) sum += __shfl_down_sync(0xffffffffu, sum, o);
            if (lane == 0) g_vcqsum[n * AA + a] = sum;
        }
    }
}

// ---------------- ctx-a: hck + t1 + ckdot partials -------------------------
__global__ __launch_bounds__(256) void k_ctx_a(
        const float* __restrict__ uk_W, const float* __restrict__ u_q1W,
        const float* __restrict__ u_q1b, const float* __restrict__ vck,
        const float* __restrict__ bnc_g, const float* __restrict__ bnc_b,
        const float* __restrict__ bnc_m, const float* __restrict__ bnc_v) {
    int n = blockIdx.y, qt = blockIdx.x;
    int tid = threadIdx.x;
    int qi = tid & 31, sl = tid >> 5;
    int q = qt * 32 + qi;

    __shared__ float c_sh[16 * 384];
    __shared__ float part[8 * 16 * 33];

    for (int i = tid; i < 16 * 384; i += 256) {
        int b = i / 384, l = i - b * 384;
        c_sh[i] = g_c[((size_t)b * CC + n * DD) * 2 + l];
    }
    __syncthreads();

    float ak[16], aq[16];
#pragma unroll
    for (int b = 0; b < 16; b++) { ak[b] = 0.f; aq[b] = 0.f; }
    {
        const float* uk = uk_W + ((size_t)n * 384) * QQ + q;
        const float* u1 = u_q1W + ((size_t)n * 384) * QQ + q;
        int l0 = sl * 48;
        for (int l = l0; l < l0 + 48; l++) {
            float wk = uk[(size_t)l * QQ];
            float w1 = u1[(size_t)l * QQ];
            const float* cb = c_sh + l;
#pragma unroll
            for (int b = 0; b < 16; b++) {
                float cv = cb[b * 384];
                ak[b] = fmaf(cv, wk, ak[b]);
                aq[b] = fmaf(cv, w1, aq[b]);
            }
        }
    }

#pragma unroll
    for (int b = 0; b < 16; b++) part[(sl * 16 + b) * 33 + qi] = ak[b];
    __syncthreads();
    {
        int bp = tid >> 5;
        float s0 = 0.f, s1 = 0.f;
#pragma unroll
        for (int s = 0; s < 8; s++) {
            s0 += part[(s * 16 + bp) * 33 + qi];
            s1 += part[(s * 16 + bp + 8) * 33 + qi];
        }
        g_hck[((size_t)(bp * NH + n)) * QQ + q] = s0;
        g_hck[((size_t)((bp + 8) * NH + n)) * QQ + q] = s1;

        float vckq = vck[n * QQ + q];
        float p0 = s0 * vckq, p1 = s1 * vckq;
#pragma unroll
        for (int o = 16; o > 0; o >>= 1) {
            p0 += __shfl_down_sync(0xffffffffu, p0, o);
            p1 += __shfl_down_sync(0xffffffffu, p1, o);
        }
        if (qi == 0) {
            g_ckdotp[(bp * NH + n) * 8 + qt] = p0;
            g_ckdotp[((bp + 8) * NH + n) * 8 + qt] = p1;
        }
    }
    __syncthreads();

#pragma unroll
    for (int b = 0; b < 16; b++) part[(sl * 16 + b) * 33 + qi] = aq[b];
    __syncthreads();
    {
        int bp = tid >> 5;
        float s0 = 0.f, s1 = 0.f;
#pragma unroll
        for (int s = 0; s < 8; s++) {
            s0 += part[(s * 16 + bp) * 33 + qi];
            s1 += part[(s * 16 + bp + 8) * 33 + qi];
        }
        float bias = u_q1b[n * QQ + q];
        float grs = bnc_g[q] * rsqrtf(bnc_v[q] + 1e-5f);
        float beta = bnc_b[q] - grs * bnc_m[q];
        float r0 = fmaxf(s0 + bias, 0.f);
        float r1 = fmaxf(s1 + bias, 0.f);
        g_t1[((size_t)(bp * NH + n)) * QQ + q] = tanhf(fmaf(grs, r0, beta));
        g_t1[((size_t)((bp + 8) * NH + n)) * QQ + q] = tanhf(fmaf(grs, r1, beta));
    }
}

// ---------------- ctx-b: cq2 + vcqdot partials ------------------------------
__global__ __launch_bounds__(256) void k_ctx_b(const float* __restrict__ u_q2) {
    int n = blockIdx.y, at = blockIdx.x;
    int tid = threadIdx.x;
    int ai = tid & 31, msl = tid >> 5;
    int a = at * 32 + ai;

    __shared__ float t1_sh[16 * 256];
    __shared__ float part[8 * 16 * 33];

    for (int i = tid; i < 16 * 256; i += 256) {
        int b = i >> 8, m = i & 255;
        t1_sh[i] = g_t1[((size_t)(b * NH + n)) * QQ + m];
    }
    __syncthreads();

    float acc[16];
#pragma unroll
    for (int b = 0; b < 16; b++) acc[b] = 0.f;
    {
        const float* u2 = u_q2 + (size_t)n * QQ * AA + a;
        int m0 = msl * 32;
        for (int m = m0; m < m0 + 32; m++) {
            float w = u2[(size_t)m * AA];
            const float* tb = t1_sh + m;
#pragma unroll
            for (int b = 0; b < 16; b++)
                acc[b] = fmaf(tb[b * 256], w, acc[b]);
        }
    }
#pragma unroll
    for (int b = 0; b < 16; b++) part[(msl * 16 + b) * 33 + ai] = acc[b];
    __syncthreads();
    {
        int bp = tid >> 5;
        float s0 = 0.f, s1 = 0.f;
#pragma unroll
        for (int s = 0; s < 8; s++) {
            s0 += part[(s * 16 + bp) * 33 + ai];
            s1 += part[(s * 16 + bp + 8) * 33 + ai];
        }
        g_cq2[((size_t)(bp * NH + n)) * AA + a] = s0;
        g_cq2[((size_t)((bp + 8) * NH + n)) * AA + a] = s1;

        float vs = g_vcqsum[n * AA + a];
        float p0 = s0 * vs, p1 = s1 * vs;
#pragma unroll
        for (int o = 16; o > 0; o >>= 1) {
            p0 += __shfl_down_sync(0xffffffffu, p0, o);
            p1 += __shfl_down_sync(0xffffffffu, p1, o);
        }
        if (ai == 0) {
            g_vcqdotp[(bp * NH + n) * 6 + at] = p0;
            g_vcqdotp[((bp + 8) * NH + n) * 6 + at] = p1;
        }
    }
}

// ---------------- K3: fused scores + pool, k2 register-resident -------------
// smem (210,464 B, 1 CTA/SM):
//  SM_XS [0, 51200):          x tile bf16 [128][200]; later dump0 (stride 100)
//  SM_QT [51200, 152576):     full qT bf16 [192][264]; rows0-95 -> dump1 later
//  SM_W1A/B [152576, 203776): 2x 25.6K W1 chunk buffers
//  SM_AUX [203776, ...)
#define XS_STRIDE 200
#define QT_STRIDE 264
#define SS_STRIDE 100
#define SM_XS 0
#define SM_QT 51200
#define SM_W1A 152576
#define SM_W1B 178176
#define SM_AUX 203776
#define AXH_C4   (SM_AUX + 0)      // float4 per q-col: (hck, kbv, grs, beta)
#define AXH_VHK  (SM_AUX + 4096)
#define AXH_QB   (SM_AUX + 5120)
#define AXH_CQ2  (SM_AUX + 5888)
#define AXH_SCAL (SM_AUX + 6656)
#define SMEM_SC  (SM_AUX + 6688)

__global__ __launch_bounds__(256) void k_scores_mma(
        const float* __restrict__ ht, const float* __restrict__ kb,
        const float* __restrict__ bg, const float* __restrict__ bbias,
        const float* __restrict__ bm, const float* __restrict__ bv,
        const float* __restrict__ vhk, const float* __restrict__ qb) {
    extern __shared__ char smem[];
    uint32_t sb = smem_u32(smem);
    int tid = threadIdx.x;
    int w = tid >> 5, lane = tid & 31;
    int bn = blockIdx.y;
    int b = bn >> 3, n = bn & 7;
    int t0 = blockIdx.x * 128;
    int r0 = w * 16 + (lane >> 2);

    // group0: W1 chunk 0 (64 q x 192 d)
    {
        const uint4* wsrc = (const uint4*)(g_w1t + (size_t)n * QQ * DD);
#pragma unroll
        for (int it = 0; it < 6; it++) {
            int idx = it * 256 + tid;
            int row = idx / 24, c8 = idx - row * 24;
            CP_ASYNC16(sb + SM_W1A + (row * XS_STRIDE + c8 * 8) * 2, wsrc + idx);
        }
        CP_COMMIT();
    }
    // group1: FULL qT (192 rows x 256 q) — per-head constant, L2-hot
    {
        const uint4* hs = (const uint4*)(g_qTb + (size_t)n * AA * QQ);
#pragma unroll
        for (int it = 0; it < 24; it++) {
            int idx = it * 256 + tid;            // 192 rows x 32 uint4
            int row = idx >> 5, c8 = idx & 31;
            CP_ASYNC16(sb + SM_QT + (row * QT_STRIDE + c8 * 8) * 2, hs + idx);
        }
        CP_COMMIT();
    }

    // aux constants + per-bn scalars
    {
        int i = tid;
        float g = bg[i];
        float grs = g * rsqrtf(bv[i] + 1e-5f);
        ((float4*)(smem + AXH_C4))[i] = make_float4(
            g_hck[(size_t)bn * QQ + i], kb[n * QQ + i], grs, bbias[i] - grs * bm[i]);
        ((float*)(smem + AXH_VHK))[i] = vhk[n * QQ + i];
        if (i < AA) {
            ((float*)(smem + AXH_QB))[i] = qb[n * AA + i];
            ((float*)(smem + AXH_CQ2))[i] = g_cq2[(size_t)bn * AA + i];
        }
        if (i == 0) {
            float qd = 0.f;
#pragma unroll
            for (int k = 0; k < 8; k++) qd += g_qdotp[n * 8 + k];
            float vq = 0.f;
#pragma unroll
            for (int k = 0; k < 6; k++) vq += g_vcqdotp[bn * 6 + k];
            ((float*)(smem + AXH_SCAL))[0] = 1.f / (1.f + __expf(-(qd + vq)));
            float ck = 0.f;
#pragma unroll
            for (int k = 0; k < 8; k++) ck += g_ckdotp[bn * 8 + k];
            ((float*)(smem + AXH_SCAL))[1] = ck;
        }
    }

    // ---- x tile (128 x 192 fp32 -> bf16), zero-pad rows past TT ----
    {
        const float* xb = ht + ((size_t)b * TT + t0) * CC + n * DD;
        for (int it = 0; it < 24; it++) {
            int idx = it * 256 + tid;
            int row = idx / 48, c4 = idx - row * 48;
            float4 v = make_float4(0.f, 0.f, 0.f, 0.f);
            if (t0 + row < TT) v = *(const float4*)(xb + (size_t)row * CC + c4 * 4);
            uint2 pk = make_uint2(pack_bf(v.x, v.y), pack_bf(v.z, v.w));
            *(uint2*)(smem + SM_XS + (row * XS_STRIDE + c4 * 4) * 2) = pk;
        }
    }
    __syncthreads();

    uint32_t abase = sb + SM_XS + ((w * 16 + (lane & 15)) * XS_STRIDE + (lane >> 4) * 8) * 2;
    uint32_t boff_w1 = (((lane >> 4) * 8 + (lane & 7)) * XS_STRIDE + ((lane >> 3) & 1) * 8) * 2;

    // ---- GEMM1 over 4 q-chunks of 64; raw hk packed to registers ----------
    uint32_t k2p[64];   // 16 k16-blocks x 4 regs; A-fragments of GEMM2
    float lam0 = 0.f, lam1 = 0.f;
#pragma unroll
    for (int qc = 0; qc < 4; qc++) {
        if (qc < 3) {
            int buf = ((qc + 1) & 1) ? SM_W1B : SM_W1A;
            const uint4* wsrc = (const uint4*)(g_w1t + ((size_t)n * QQ + (qc + 1) * 64) * DD);
#pragma unroll
            for (int it = 0; it < 6; it++) {
                int idx = it * 256 + tid;
                int row = idx / 24, c8 = idx - row * 24;
                CP_ASYNC16(sb + buf + (row * XS_STRIDE + c8 * 8) * 2, wsrc + idx);
            }
            CP_COMMIT();
        }
        // waits: qc0 -> W1c0 (pending c0,qT,c1 -> wait 2); qc1 -> wait 1;
        //        qc2 -> wait 1; qc3 -> wait 0 (everything incl. qT)
        if (qc == 0) CP_WAITG(2);
        else if (qc == 3) CP_WAITG(0);
        else CP_WAITG(1);
        __syncthreads();

        uint32_t bbase = sb + ((qc & 1) ? SM_W1B : SM_W1A) + boff_w1;

        float c[4][2][4];
#pragma unroll
        for (int p = 0; p < 4; p++)
#pragma unroll
            for (int j = 0; j < 2; j++)
#pragma unroll
                for (int e = 0; e < 4; e++) c[p][j][e] = 0.f;

        for (int kk = 0; kk < 12; kk++) {
            uint32_t a[4];
            ldsm_x4(a, abase + kk * 32);
#pragma unroll
            for (int p = 0; p < 4; p++) {
                uint32_t bf[4];
                ldsm_x4(bf, bbase + p * 16 * XS_STRIDE * 2 + kk * 32);
                mma_bf16(c[p][0], a, bf[0], bf[1]);
                mma_bf16(c[p][1], a, bf[2], bf[3]);
            }
        }

        // lambda accum + pack raw hk into A-fragment layout (registers)
        const float* vhk_s = (const float*)(smem + AXH_VHK);
#pragma unroll
        for (int p = 0; p < 4; p++) {
#pragma unroll
            for (int j = 0; j < 2; j++) {
                int col = qc * 64 + p * 16 + j * 8 + 2 * (lane & 3);
                float v0 = vhk_s[col], v1 = vhk_s[col + 1];
                lam0 += c[p][j][0] * v0 + c[p][j][1] * v1;
                lam1 += c[p][j][2] * v0 + c[p][j][3] * v1;
            }
            int ib = (qc * 4 + p) * 4;
            k2p[ib + 0] = pack_bf(c[p][0][0], c[p][0][1]);   // row r0,   k 0..1 of lo8
            k2p[ib + 1] = pack_bf(c[p][0][2], c[p][0][3]);   // row r0+8, lo8
            k2p[ib + 2] = pack_bf(c[p][1][0], c[p][1][1]);   // row r0,   hi8
            k2p[ib + 3] = pack_bf(c[p][1][2], c[p][1][3]);   // row r0+8, hi8
        }
        if (qc < 3) __syncthreads();   // buffer reads done before re-fill
    }
    __syncthreads();   // GEMM1 reads of XS done; qT visible to all threads

    // ---- lambda: fully warp-local (rows owned by this warp) ----------------
    lam0 += __shfl_xor_sync(0xffffffffu, lam0, 1);
    lam0 += __shfl_xor_sync(0xffffffffu, lam0, 2);
    lam1 += __shfl_xor_sync(0xffffffffu, lam1, 1);
    lam1 += __shfl_xor_sync(0xffffffffu, lam1, 2);
    float ckd = ((const float*)(smem + AXH_SCAL))[1];
    float lamA = 1.f / (1.f + __expf(-(lam0 + ckd)));   // row r0
    float lamB = 1.f / (1.f + __expf(-(lam1 + ckd)));   // row r0+8

    // ---- activation entirely in registers + rowsums ------------------------
    float rsA = 0.f, rsB = 0.f;
    {
        const float4* c4 = (const float4*)(smem + AXH_C4);
#pragma unroll
        for (int i = 0; i < 16; i++) {
            int cbase = i * 16 + 2 * (lane & 3);
            float4 kc0 = c4[cbase], kc1 = c4[cbase + 1];
            float4 kc8 = c4[cbase + 8], kc9 = c4[cbase + 9];
#pragma unroll
            for (int r = 0; r < 4; r++) {
                const float4 ka = (r < 2) ? kc0 : kc8;
                const float4 kbb = (r < 2) ? kc1 : kc9;
                float lam = (r & 1) ? lamB : lamA;
                uint32_t v = k2p[i * 4 + r];
                float h0 = bflo(v), h1 = bfhi(v);
                float m0 = fmaf(lam, ka.x - h0, h0) + ka.y;
                float m1 = fmaf(lam, kbb.x - h1, h1) + kbb.y;
                m0 = fmaxf(m0, 0.f); m1 = fmaxf(m1, 0.f);
                float a0 = tanha(fmaf(ka.z, m0, ka.w));
                float a1 = tanha(fmaf(kbb.z, m1, kbb.w));
                if (r & 1) rsB += a0 + a1; else rsA += a0 + a1;
                k2p[i * 4 + r] = pack_bf(a0, a1);
            }
        }
    }
    rsA += __shfl_xor_sync(0xffffffffu, rsA, 1);
    rsA += __shfl_xor_sync(0xffffffffu, rsA, 2);
    rsB += __shfl_xor_sync(0xffffffffu, rsB, 1);
    rsB += __shfl_xor_sync(0xffffffffu, rsB, 2);

    float lamq = ((const float*)(smem + AXH_SCAL))[0];
    float onem = 1.f - lamq;
    float lqs = lamq * (1.f / 16.f);
    float rsa = rsA * lqs, rsb = rsB * lqs;

    // ---- GEMM2: 2 a-chunks of 96 vs qT; A from registers -------------------
    uint32_t boff_q = (((lane >> 4) * 8 + (lane & 7)) * QT_STRIDE + ((lane >> 3) & 1) * 8) * 2;
    const float* cq2_s = (const float*)(smem + AXH_CQ2);

#pragma unroll
    for (int ac = 0; ac < 2; ac++) {
        uint32_t bbase2 = sb + SM_QT + (uint32_t)(ac * 96 * QT_STRIDE * 2) + boff_q;

        float c2[6][2][4];
#pragma unroll
        for (int p = 0; p < 6; p++)
#pragma unroll
            for (int j = 0; j < 2; j++)
#pragma unroll
                for (int e = 0; e < 4; e++) c2[p][j][e] = 0.f;

#pragma unroll
        for (int kk = 0; kk < 16; kk++) {
#pragma unroll
            for (int p = 0; p < 6; p++) {
                uint32_t bf[4];
                ldsm_x4(bf, bbase2 + p * 16 * QT_STRIDE * 2 + kk * 32);
                mma_bf16(c2[p][0], &k2p[kk * 4], bf[0], bf[1]);
                mma_bf16(c2[p][1], &k2p[kk * 4], bf[2], bf[3]);
            }
        }

        if (ac == 0) __syncthreads();   // chunk-0 qT rows dead before dump1 use
        // dump: chunk0 -> XS; chunk1 -> QT base (rows 0..95 region)
        float* sdst = (float*)(smem + (ac ? SM_QT : SM_XS));
#pragma unroll
        for (int p = 0; p < 6; p++) {
#pragma unroll
            for (int j = 0; j < 2; j++) {
                int col = p * 16 + j * 8 + 2 * (lane & 3);
                float cqa = cq2_s[ac * 96 + col], cqb = cq2_s[ac * 96 + col + 1];
                *(float2*)(sdst + r0 * SS_STRIDE + col) = make_float2(
                    fmaf(onem, c2[p][j][0], rsa * cqa),
                    fmaf(onem, c2[p][j][1], rsa * cqb));
                *(float2*)(sdst + (r0 + 8) * SS_STRIDE + col) = make_float2(
                    fmaf(onem, c2[p][j][2], rsb * cqa),
                    fmaf(onem, c2[p][j][3], rsb * cqb));
            }
        }
    }
    __syncthreads();

    // ---- fused softmax partials: thread == a (192 active) -----------------
    if (tid < AA) {
        int a = tid;
        const float* ssm = (a < 96) ? (const float*)(smem + SM_XS)
                                    : (const float*)(smem + SM_QT);
        int acol = (a < 96) ? a : (a - 96);
        float qbv = ((const float*)(smem + AXH_QB))[a];
        int tmax = TT - t0; if (tmax > 128) tmax = 128;

        float M = -1e30f;
        for (int t = 0; t < tmax; t++)
            M = fmaxf(M, ssm[t * SS_STRIDE + acol]);
        M += qbv;

        float Z = 0.f, S1 = 0.f, S2 = 0.f;
        const float* vp = ht + ((size_t)b * TT + t0) * CC + n * DD + a;
#pragma unroll 4
        for (int t = 0; t < tmax; t++) {
            float s = ssm[t * SS_STRIDE + acol] + qbv;
            float wv = __expf(s - M);
            float v = vp[(size_t)t * CC];
            Z += wv; S1 += wv * v; S2 += wv * v * v;
        }
        g_pp[((size_t)bn * 16 + blockIdx.x) * AA + a] = make_float4(M, Z, S1, S2);
    }
}

// ---------------- K4: merge 16 tile partials -> output ---------------------
__global__ __launch_bounds__(192) void k_pool_merge(float* __restrict__ out) {
    int bn = blockIdx.x;
    int b = bn >> 3, n = bn & 7;
    int a = threadIdx.x;

    const float4* pp = g_pp + (size_t)bn * 16 * AA + a;
    float M = -1e30f;
#pragma unroll
    for (int s = 0; s < 16; s++) M = fmaxf(M, pp[s * AA].x);
    float Zt = 0.f, S1t = 0.f, S2t = 0.f;
#pragma unroll
    for (int s = 0; s < 16; s++) {
        float4 p = pp[s * AA];
        float c = __expf(p.x - M);
        Zt += p.y * c; S1t += p.z * c; S2t += p.w * c;
    }
    float mu = S1t / Zt;
    float ex2 = S2t / Zt;
    float rh = sqrtf(fmaxf(ex2 - mu * mu, 1e-9f));
    out[(size_t)b * (2 * CC) + n * DD + a] = mu;
    out[(size_t)b * (2 * CC) + CC + n * DD + a] = rh;
}

// ---------------- launcher ------------------------------------------------
extern "C" void kernel_launch(void* const* d_in, const int* in_sizes, int n_in,
                              void* d_out, int out_size) {
    const float* ht       = (const float*)d_in[0];
    const float* k_proj_W = (const float*)d_in[1];
    const float* query    = (const float*)d_in[2];
    const float* uk_W     = (const float*)d_in[3];
    const float* u_q1W    = (const float*)d_in[4];
    const float* u_q2     = (const float*)d_in[5];
    const float* vhq      = (const float*)d_in[6];
    const float* vhk      = (const float*)d_in[7];
    const float* vcq      = (const float*)d_in[8];
    const float* vck      = (const float*)d_in[9];
    const float* k_proj_b = (const float*)d_in[10];
    const float* q_b      = (const float*)d_in[11];
    const float* u_q1b    = (const float*)d_in[12];
    const float* bnc_g    = (const float*)d_in[13];
    const float* bnc_b    = (const float*)d_in[14];
    const float* bnc_m    = (const float*)d_in[15];
    const float* bnc_v    = (const float*)d_in[16];
    const float* bnk_g    = (const float*)d_in[17];
    const float* bnk_b    = (const float*)d_in[18];
    const float* bnk_m    = (const float*)d_in[19];
    const float* bnk_v    = (const float*)d_in[20];
    float* out = (float*)d_out;

    static int smem_set = 0;
    if (!smem_set) {
        cudaFuncSetAttribute(k_scores_mma,
                             cudaFuncAttributeMaxDynamicSharedMemorySize, SMEM_SC);
        smem_set = 1;
    }

    // launch 1: fused front
    k_front<<<1216, 256>>>(ht, k_proj_W, query, vhq, vcq);

    // launch 2: ctx_a
    dim3 ga(8, NH);
    k_ctx_a<<<ga, 256>>>(uk_W, u_q1W, u_q1b, vck, bnc_g, bnc_b, bnc_m, bnc_v);

    // launch 3: ctx_b
    dim3 gb(6, NH);
    k_ctx_b<<<gb, 256>>>(u_q2);

    // launch 4 (ncu-captured): fused scores, k2 register-resident
    dim3 gsc(16, BB * NH);
    k_scores_mma<<<gsc, 256, SMEM_SC>>>(ht, k_proj_b, bnk_g, bnk_b, bnk_m, bnk_v,
                                        vhk, q_b);

    // launch 5: merge
    k_pool_merge<<<BB * NH, AA>>>(out);
}

// round 17
// speedup vs baseline: 1.3090x; 1.3090x over previous
#include <cuda_runtime.h>
#include <cuda_bf16.h>
#include <math.h>
#include <stdint.h>

// Problem constants
#define BB 16
#define TT 2000
#define CC 1536
#define NH 8
#define DD 192
#define QQ 256
#define AA 192

// ===================== warp-MMA helpers (sm_80+ baseline) ==================
__device__ __forceinline__ uint32_t smem_u32(const void* p) {
    uint32_t a;
    asm("{ .reg .u64 t; cvta.to.shared.u64 t, %1; cvt.u32.u64 %0, t; }"
        : "=r"(a) : "l"(p));
    return a;
}
__device__ __forceinline__ void ldsm_x4(uint32_t r[4], uint32_t addr) {
    asm volatile("ldmatrix.sync.aligned.m8n8.x4.shared.b16 {%0,%1,%2,%3}, [%4];"
                 : "=r"(r[0]), "=r"(r[1]), "=r"(r[2]), "=r"(r[3]) : "r"(addr));
}
__device__ __forceinline__ void mma_bf16(float c[4], const uint32_t a[4],
                                         uint32_t b0, uint32_t b1) {
    asm volatile("mma.sync.aligned.m16n8k16.row.col.f32.bf16.bf16.f32 "
                 "{%0,%1,%2,%3}, {%4,%5,%6,%7}, {%8,%9}, {%0,%1,%2,%3};"
                 : "+f"(c[0]), "+f"(c[1]), "+f"(c[2]), "+f"(c[3])
                 : "r"(a[0]), "r"(a[1]), "r"(a[2]), "r"(a[3]), "r"(b0), "r"(b1));
}
__device__ __forceinline__ uint32_t pack_bf(float lo, float hi) {
    uint32_t r;
    asm("cvt.rn.bf16x2.f32 %0, %1, %2;" : "=r"(r) : "f"(hi), "f"(lo));
    return r;
}
__device__ __forceinline__ float bflo(uint32_t u) { return __uint_as_float(u << 16); }
__device__ __forceinline__ float bfhi(uint32_t u) { return __uint_as_float(u & 0xffff0000u); }
__device__ __forceinline__ float tanha(float x) {
    float r; asm("tanh.approx.f32 %0, %1;" : "=f"(r) : "f"(x)); return r;
}
#define CP_ASYNC16(dst, src) \
    asm volatile("cp.async.cg.shared.global [%0], [%1], 16;" :: "r"(dst), "l"(src))
#define CP_COMMIT() asm volatile("cp.async.commit_group;" ::: "memory")
#define CP_WAIT0() asm volatile("cp.async.wait_group 0;" ::: "memory")
#define CP_WAIT1() asm volatile("cp.async.wait_group 1;" ::: "memory")

// ---------------- scratch (device globals: no allocations allowed) --------
__device__ float g_c[BB * CC * 2];
__device__ float g_hck[BB * NH * QQ];
__device__ float g_t1[BB * NH * QQ];
__device__ float g_cq2[BB * NH * AA];
__device__ float g_vcqsum[NH * AA];
__device__ float g_ckdotp[BB * NH * 8];
__device__ float g_vcqdotp[BB * NH * 6];
__device__ float g_qdotp[NH * 8];
__device__ __nv_bfloat16 g_w1t[NH * QQ * DD];               // W1^T [n][q][d] bf16
__device__ __nv_bfloat16 g_qTb[NH * AA * QQ];               // query^T/sqrt(Q) bf16
__device__ float4 g_pp[BB * NH * 16 * AA];                  // pool partials per tile

// ---------------- K-front: stats + prepw + prepq + qdot (one launch) -------
__global__ __launch_bounds__(256) void k_front(
        const float* __restrict__ ht, const float* __restrict__ W1,
        const float* __restrict__ query, const float* __restrict__ vhq,
        const float* __restrict__ vcq) {
    __shared__ float shbuf[1088];
    int bid = blockIdx.x;
    int tid = threadIdx.x;

    if (bid < 384) {
        int b = bid / 24, cht = bid % 24;
        int c = tid & 63, sl = tid >> 6;
        int ch = cht * 64 + c;
        float s = 0.f, s2 = 0.f;
        const float* p = ht + (size_t)b * TT * CC + ch;
        for (int t = sl; t < TT; t += 4) {
            float v = p[(size_t)t * CC];
            s += v; s2 += v * v;
        }
        shbuf[sl * 64 + c] = s;
        shbuf[256 + sl * 64 + c] = s2;
        __syncthreads();
        if (sl == 0) {
            for (int j = 1; j < 4; j++) { s += shbuf[j * 64 + c]; s2 += shbuf[256 + j * 64 + c]; }
            float mean = s * (1.f / TT);
            float var = (s2 - (float)TT * mean * mean) * (1.f / (TT - 1));
            float sd = sqrtf(fmaxf(var, 0.f));
            g_c[((size_t)b * CC + ch) * 2 + 0] = mean;
            g_c[((size_t)b * CC + ch) * 2 + 1] = sd;
        }
    } else if (bid < 768) {
        int idx = bid - 384;
        int tile = idx % 48, n = idx / 48;
        int d0 = (tile % 6) * 32, q0 = (tile / 6) * 32;
        int tx = tid & 31, ty = tid >> 5;
#pragma unroll
        for (int j = 0; j < 4; j++)
            shbuf[(ty + j * 8) * 33 + tx] = W1[((size_t)n * DD + d0 + ty + j * 8) * QQ + q0 + tx];
        __syncthreads();
#pragma unroll
        for (int j = 0; j < 4; j++)
            g_w1t[((size_t)n * QQ + q0 + ty + j * 8) * DD + d0 + tx] =
                __float2bfloat16_rn(shbuf[tx * 33 + ty + j * 8]);
    } else if (bid < 1152) {
        int idx = bid - 768;
        int tile = idx % 48, n = idx / 48;
        int a0 = (tile % 6) * 32, q0 = (tile / 6) * 32;
        int tx = tid & 31, ty = tid >> 5;
#pragma unroll
        for (int j = 0; j < 4; j++)
            shbuf[(ty + j * 8) * 33 + tx] = query[((size_t)n * QQ + q0 + ty + j * 8) * AA + a0 + tx];
        __syncthreads();
#pragma unroll
        for (int j = 0; j < 4; j++)
            g_qTb[((size_t)n * AA + a0 + ty + j * 8) * QQ + q0 + tx] =
                __float2bfloat16_rn(shbuf[tx * 33 + ty + j * 8] * (1.f / 16.f));
    } else {
        int idx = bid - 1152;
        int s = idx % 8, n = idx / 8;
        float acc = 0.f;
        int base = s * (AA * QQ / 8);
        for (int ii = tid; ii < AA * QQ / 8; ii += 256) {
            int i = base + ii;
            int a = i >> 8, q = i & 255;
            acc += query[(n * QQ + q) * AA + a] * vhq[n * AA * QQ + i];
        }
        shbuf[tid] = acc;
        __syncthreads();
        for (int off = 128; off > 0; off >>= 1) {
            if (tid < off) shbuf[tid] += shbuf[tid + off];
            __syncthreads();
        }
        if (tid == 0) g_qdotp[n * 8 + s] = shbuf[0];

        int w = tid >> 5, lane = tid & 31;
        for (int r = w; r < AA / 8; r += 8) {
            int a = s * (AA / 8) + r;
            const float* vp = vcq + ((size_t)n * AA + a) * QQ;
            float sum = 0.f;
            for (int q = lane; q < QQ; q += 32) sum += vp[q];
#pragma unroll
            for (int o = 16; o > 0; o >>= 1) sum += __shfl_down_sync(0xffffffffu, sum, o);
            if (lane == 0) g_vcqsum[n * AA + a] = sum;
        }
    }
}

// ---------------- ctx-a: hck + t1 + ckdot partials -------------------------
__global__ __launch_bounds__(256) void k_ctx_a(
        const float* __restrict__ uk_W, const float* __restrict__ u_q1W,
        const float* __restrict__ u_q1b, const float* __restrict__ vck,
        const float* __restrict__ bnc_g, const float* __restrict__ bnc_b,
        const float* __restrict__ bnc_m, const float* __restrict__ bnc_v) {
    int n = blockIdx.y, qt = blockIdx.x;
    int tid = threadIdx.x;
    int qi = tid & 31, sl = tid >> 5;
    int q = qt * 32 + qi;

    __shared__ float c_sh[16 * 384];
    __shared__ float part[8 * 16 * 33];

    for (int i = tid; i < 16 * 384; i += 256) {
        int b = i / 384, l = i - b * 384;
        c_sh[i] = g_c[((size_t)b * CC + n * DD) * 2 + l];
    }
    __syncthreads();

    float ak[16], aq[16];
#pragma unroll
    for (int b = 0; b < 16; b++) { ak[b] = 0.f; aq[b] = 0.f; }
    {
        const float* uk = uk_W + ((size_t)n * 384) * QQ + q;
        const float* u1 = u_q1W + ((size_t)n * 384) * QQ + q;
        int l0 = sl * 48;
        for (int l = l0; l < l0 + 48; l++) {
            float wk = uk[(size_t)l * QQ];
            float w1 = u1[(size_t)l * QQ];
            const float* cb = c_sh + l;
#pragma unroll
            for (int b = 0; b < 16; b++) {
                float cv = cb[b * 384];
                ak[b] = fmaf(cv, wk, ak[b]);
                aq[b] = fmaf(cv, w1, aq[b]);
            }
        }
    }

#pragma unroll
    for (int b = 0; b < 16; b++) part[(sl * 16 + b) * 33 + qi] = ak[b];
    __syncthreads();
    {
        int bp = tid >> 5;
        float s0 = 0.f, s1 = 0.f;
#pragma unroll
        for (int s = 0; s < 8; s++) {
            s0 += part[(s * 16 + bp) * 33 + qi];
            s1 += part[(s * 16 + bp + 8) * 33 + qi];
        }
        g_hck[((size_t)(bp * NH + n)) * QQ + q] = s0;
        g_hck[((size_t)((bp + 8) * NH + n)) * QQ + q] = s1;

        float vckq = vck[n * QQ + q];
        float p0 = s0 * vckq, p1 = s1 * vckq;
#pragma unroll
        for (int o = 16; o > 0; o >>= 1) {
            p0 += __shfl_down_sync(0xffffffffu, p0, o);
            p1 += __shfl_down_sync(0xffffffffu, p1, o);
        }
        if (qi == 0) {
            g_ckdotp[(bp * NH + n) * 8 + qt] = p0;
            g_ckdotp[((bp + 8) * NH + n) * 8 + qt] = p1;
        }
    }
    __syncthreads();

#pragma unroll
    for (int b = 0; b < 16; b++) part[(sl * 16 + b) * 33 + qi] = aq[b];
    __syncthreads();
    {
        int bp = tid >> 5;
        float s0 = 0.f, s1 = 0.f;
#pragma unroll
        for (int s = 0; s < 8; s++) {
            s0 += part[(s * 16 + bp) * 33 + qi];
            s1 += part[(s * 16 + bp + 8) * 33 + qi];
        }
        float bias = u_q1b[n * QQ + q];
        float grs = bnc_g[q] * rsqrtf(bnc_v[q] + 1e-5f);
        float beta = bnc_b[q] - grs * bnc_m[q];
        float r0 = fmaxf(s0 + bias, 0.f);
        float r1 = fmaxf(s1 + bias, 0.f);
        g_t1[((size_t)(bp * NH + n)) * QQ + q] = tanhf(fmaf(grs, r0, beta));
        g_t1[((size_t)((bp + 8) * NH + n)) * QQ + q] = tanhf(fmaf(grs, r1, beta));
    }
}

// ---------------- ctx-b: cq2 + vcqdot partials ------------------------------
__global__ __launch_bounds__(256) void k_ctx_b(const float* __restrict__ u_q2) {
    int n = blockIdx.y, at = blockIdx.x;
    int tid = threadIdx.x;
    int ai = tid & 31, msl = tid >> 5;
    int a = at * 32 + ai;

    __shared__ float t1_sh[16 * 256];
    __shared__ float part[8 * 16 * 33];

    for (int i = tid; i < 16 * 256; i += 256) {
        int b = i >> 8, m = i & 255;
        t1_sh[i] = g_t1[((size_t)(b * NH + n)) * QQ + m];
    }
    __syncthreads();

    float acc[16];
#pragma unroll
    for (int b = 0; b < 16; b++) acc[b] = 0.f;
    {
        const float* u2 = u_q2 + (size_t)n * QQ * AA + a;
        int m0 = msl * 32;
        for (int m = m0; m < m0 + 32; m++) {
            float w = u2[(size_t)m * AA];
            const float* tb = t1_sh + m;
#pragma unroll
            for (int b = 0; b < 16; b++)
                acc[b] = fmaf(tb[b * 256], w, acc[b]);
        }
    }
#pragma unroll
    for (int b = 0; b < 16; b++) part[(msl * 16 + b) * 33 + ai] = acc[b];
    __syncthreads();
    {
        int bp = tid >> 5;
        float s0 = 0.f, s1 = 0.f;
#pragma unroll
        for (int s = 0; s < 8; s++) {
            s0 += part[(s * 16 + bp) * 33 + ai];
            s1 += part[(s * 16 + bp + 8) * 33 + ai];
        }
        g_cq2[((size_t)(bp * NH + n)) * AA + a] = s0;
        g_cq2[((size_t)((bp + 8) * NH + n)) * AA + a] = s1;

        float vs = g_vcqsum[n * AA + a];
        float p0 = s0 * vs, p1 = s1 * vs;
#pragma unroll
        for (int o = 16; o > 0; o >>= 1) {
            p0 += __shfl_down_sync(0xffffffffu, p0, o);
            p1 += __shfl_down_sync(0xffffffffu, p1, o);
        }
        if (ai == 0) {
            g_vcqdotp[(bp * NH + n) * 6 + at] = p0;
            g_vcqdotp[((bp + 8) * NH + n) * 6 + at] = p1;
        }
    }
}

// ---------------- K3: fused scores + softmax-partial kernel ----------------
#define XS_STRIDE 200
#define HK_STRIDE 264
#define SS_STRIDE 100
#define SM_XS 0
#define SM_HK 51200
#define SM_W1A 118784
#define SM_W1B 144384
#define SM_AUX 169984
#define AXH_HCK  (SM_AUX + 0)
#define AXH_KBV  (SM_AUX + 1024)
#define AXH_GRS  (SM_AUX + 2048)
#define AXH_BETA (SM_AUX + 3072)
#define AXH_VHK  (SM_AUX + 4096)
#define AXH_QB   (SM_AUX + 5120)
#define AXH_CQ2  (SM_AUX + 5888)
#define AXH_RS   (SM_AUX + 6656)
#define AXH_LAM  (SM_AUX + 7680)
#define AXH_SCAL (SM_AUX + 8192)
#define SMEM_SC  (SM_AUX + 8448)

__global__ __launch_bounds__(256) void k_scores_mma(
        const float* __restrict__ ht, const float* __restrict__ kb,
        const float* __restrict__ bg, const float* __restrict__ bbias,
        const float* __restrict__ bm, const float* __restrict__ bv,
        const float* __restrict__ vhk, const float* __restrict__ qb) {
    extern __shared__ char smem[];
    uint32_t sb = smem_u32(smem);
    int tid = threadIdx.x;
    int w = tid >> 5, lane = tid & 31;
    int bn = blockIdx.y;
    int b = bn >> 3, n = bn & 7;
    int t0 = blockIdx.x * 128;

    // kick off W1 chunk 0 async load immediately
    {
        const uint4* wsrc = (const uint4*)(g_w1t + (size_t)n * QQ * DD);
#pragma unroll
        for (int it = 0; it < 6; it++) {
            int idx = it * 256 + tid;
            int row = idx / 24, c8 = idx - row * 24;
            CP_ASYNC16(sb + SM_W1A + (row * XS_STRIDE + c8 * 8) * 2, wsrc + idx);
        }
        CP_COMMIT();
    }

    // aux constant arrays + per-bn scalars
    {
        int i = tid;
        float g = bg[i];
        float grs = g * rsqrtf(bv[i] + 1e-5f);
        ((float*)(smem + AXH_GRS))[i] = grs;
        ((float*)(smem + AXH_BETA))[i] = bbias[i] - grs * bm[i];
        ((float*)(smem + AXH_HCK))[i] = g_hck[(size_t)bn * QQ + i];
        ((float*)(smem + AXH_KBV))[i] = kb[n * QQ + i];
        ((float*)(smem + AXH_VHK))[i] = vhk[n * QQ + i];
        if (i < AA) {
            ((float*)(smem + AXH_QB))[i] = qb[n * AA + i];
            ((float*)(smem + AXH_CQ2))[i] = g_cq2[(size_t)bn * AA + i];
        }
        if (i == 0) {
            float qd = 0.f;
#pragma unroll
            for (int k = 0; k < 8; k++) qd += g_qdotp[n * 8 + k];
            float vq = 0.f;
#pragma unroll
            for (int k = 0; k < 6; k++) vq += g_vcqdotp[bn * 6 + k];
            ((float*)(smem + AXH_SCAL))[0] = 1.f / (1.f + __expf(-(qd + vq)));  // lamq
            float ck = 0.f;
#pragma unroll
            for (int k = 0; k < 8; k++) ck += g_ckdotp[bn * 8 + k];
            ((float*)(smem + AXH_SCAL))[1] = ck;
        }
    }

    // ---- load x tile (fp32 -> bf16), rows padded with zeros past TT ----
    {
        const float* xb = ht + ((size_t)b * TT + t0) * CC + n * DD;
        for (int it = 0; it < 24; it++) {
            int idx = it * 256 + tid;
            int row = idx / 48, c4 = idx - row * 48;
            float4 v = make_float4(0.f, 0.f, 0.f, 0.f);
            if (t0 + row < TT) v = *(const float4*)(xb + (size_t)row * CC + c4 * 4);
            uint2 pk = make_uint2(pack_bf(v.x, v.y), pack_bf(v.z, v.w));
            *(uint2*)(smem + SM_XS + (row * XS_STRIDE + c4 * 4) * 2) = pk;
        }
    }

    uint32_t abase = sb + SM_XS + ((w * 16 + (lane & 15)) * XS_STRIDE + (lane >> 4) * 8) * 2;
    uint32_t boff_w1 = (((lane >> 4) * 8 + (lane & 7)) * XS_STRIDE + ((lane >> 3) & 1) * 8) * 2;

    // ---- GEMM1 over 4 q-chunks of 64, double-buffered W1; lambda in regs --
    // inner loop software-pipelined: next-kk fragments loaded before this-kk MMAs
    float lam0 = 0.f, lam1 = 0.f;
    for (int qc = 0; qc < 4; qc++) {
        if (qc < 3) {
            int buf = ((qc + 1) & 1) ? SM_W1B : SM_W1A;
            const uint4* wsrc = (const uint4*)(g_w1t + ((size_t)n * QQ + (qc + 1) * 64) * DD);
#pragma unroll
            for (int it = 0; it < 6; it++) {
                int idx = it * 256 + tid;
                int row = idx / 24, c8 = idx - row * 24;
                CP_ASYNC16(sb + buf + (row * XS_STRIDE + c8 * 8) * 2, wsrc + idx);
            }
            CP_COMMIT();
            CP_WAIT1();
        } else {
            CP_WAIT0();
        }
        __syncthreads();

        uint32_t bbase = sb + ((qc & 1) ? SM_W1B : SM_W1A) + boff_w1;

        float c[4][2][4];
#pragma unroll
        for (int p = 0; p < 4; p++)
#pragma unroll
            for (int j = 0; j < 2; j++)
#pragma unroll
                for (int e = 0; e < 4; e++) c[p][j][e] = 0.f;

        uint32_t aC[4], bC[4][4];
        ldsm_x4(aC, abase);
#pragma unroll
        for (int p = 0; p < 4; p++) ldsm_x4(bC[p], bbase + p * 16 * XS_STRIDE * 2);

#pragma unroll
        for (int kk = 0; kk < 12; kk++) {
            uint32_t aN[4], bN[4][4];
            if (kk < 11) {
                ldsm_x4(aN, abase + (kk + 1) * 32);
#pragma unroll
                for (int p = 0; p < 4; p++)
                    ldsm_x4(bN[p], bbase + p * 16 * XS_STRIDE * 2 + (kk + 1) * 32);
            }
#pragma unroll
            for (int p = 0; p < 4; p++) {
                mma_bf16(c[p][0], aC, bC[p][0], bC[p][1]);
                mma_bf16(c[p][1], aC, bC[p][2], bC[p][3]);
            }
            if (kk < 11) {
#pragma unroll
                for (int e = 0; e < 4; e++) aC[e] = aN[e];
#pragma unroll
                for (int p = 0; p < 4; p++)
#pragma unroll
                    for (int e = 0; e < 4; e++) bC[p][e] = bN[p][e];
            }
        }

        const float* vhk_s = (const float*)(smem + AXH_VHK);
        int r0 = w * 16 + (lane >> 2);
#pragma unroll
        for (int p = 0; p < 4; p++) {
#pragma unroll
            for (int j = 0; j < 2; j++) {
                int col = qc * 64 + p * 16 + j * 8 + 2 * (lane & 3);
                float v0 = vhk_s[col], v1 = vhk_s[col + 1];
                lam0 += c[p][j][0] * v0 + c[p][j][1] * v1;
                lam1 += c[p][j][2] * v0 + c[p][j][3] * v1;
                *(uint32_t*)(smem + SM_HK + (r0 * HK_STRIDE + col) * 2) =
                    pack_bf(c[p][j][0], c[p][j][1]);
                *(uint32_t*)(smem + SM_HK + ((r0 + 8) * HK_STRIDE + col) * 2) =
                    pack_bf(c[p][j][2], c[p][j][3]);
            }
        }
        __syncthreads();
    }

    // prefetch qT chunk 0 (a 0..95) into XS region (L2-hot, per-head const)
    {
        const uint4* hs = (const uint4*)(g_qTb + (size_t)n * AA * QQ);
#pragma unroll
        for (int it = 0; it < 12; it++) {
            int idx = it * 256 + tid;
            int row = idx / 32, c8 = idx - row * 32;
            CP_ASYNC16(sb + SM_XS + (row * HK_STRIDE + c8 * 8) * 2, hs + idx);
        }
        CP_COMMIT();
    }

    // lambda finalize
    lam0 += __shfl_xor_sync(0xffffffffu, lam0, 1);
    lam0 += __shfl_xor_sync(0xffffffffu, lam0, 2);
    lam1 += __shfl_xor_sync(0xffffffffu, lam1, 1);
    lam1 += __shfl_xor_sync(0xffffffffu, lam1, 2);
    {
        float ckd = ((const float*)(smem + AXH_SCAL))[1];
        if ((lane & 3) == 0) {
            float* lam_sh = (float*)(smem + AXH_LAM);
            lam_sh[w * 16 + (lane >> 2)] = 1.f / (1.f + __expf(-(lam0 + ckd)));
            lam_sh[w * 16 + (lane >> 2) + 8] = 1.f / (1.f + __expf(-(lam1 + ckd)));
        }
    }
    __syncthreads();

    // ---- activation in place + k2 rowsums (for rank-1 term) ----
    {
        int row = w * 16 + (lane >> 1);
        int cb = (lane & 1) * 128;
        float lam = ((const float*)(smem + AXH_LAM))[row];
        const float* hck_s = (const float*)(smem + AXH_HCK);
        const float* kbv_s = (const float*)(smem + AXH_KBV);
        const float* grs_s = (const float*)(smem + AXH_GRS);
        const float* bet_s = (const float*)(smem + AXH_BETA);
        uint32_t* hp = (uint32_t*)(smem + SM_HK + (row * HK_STRIDE + cb) * 2);
        float rs_acc = 0.f;
        for (int j = 0; j < 16; j++) {
            uint4 v = *(uint4*)(hp + j * 4);
            uint32_t* vr = (uint32_t*)&v;
#pragma unroll
            for (int e = 0; e < 4; e++) {
                int c0 = cb + j * 8 + 2 * e;
                float h0 = bflo(vr[e]), h1 = bfhi(vr[e]);
                float m0 = fmaf(lam, hck_s[c0] - h0, h0) + kbv_s[c0];
                float m1 = fmaf(lam, hck_s[c0 + 1] - h1, h1) + kbv_s[c0 + 1];
                m0 = fmaxf(m0, 0.f); m1 = fmaxf(m1, 0.f);
                float a0 = tanha(fmaf(grs_s[c0], m0, bet_s[c0]));
                float a1 = tanha(fmaf(grs_s[c0 + 1], m1, bet_s[c0 + 1]));
                rs_acc += a0 + a1;
                vr[e] = pack_bf(a0, a1);
            }
            *(uint4*)(hp + j * 4) = v;
        }
        ((float*)(smem + AXH_RS))[(lane & 1) * 128 + row] = rs_acc;
    }

    // ---- GEMM2 over 2 a-chunks of 96 vs qT; rank-1 fused in epilogue ------
    uint32_t abase2 = sb + SM_HK + ((w * 16 + (lane & 15)) * HK_STRIDE + (lane >> 4) * 8) * 2;
    uint32_t boff_hcq = (((lane >> 4) * 8 + (lane & 7)) * HK_STRIDE + ((lane >> 3) & 1) * 8) * 2;
    int r0 = w * 16 + (lane >> 2);

    for (int ac = 0; ac < 2; ac++) {
        if (ac == 0) {
            const uint4* hs = (const uint4*)(g_qTb + ((size_t)n * AA + 96) * QQ);
#pragma unroll
            for (int it = 0; it < 12; it++) {
                int idx = it * 256 + tid;
                int row = idx / 32, c8 = idx - row * 32;
                CP_ASYNC16(sb + SM_W1A + (row * HK_STRIDE + c8 * 8) * 2, hs + idx);
            }
            CP_COMMIT();
            CP_WAIT1();
        } else {
            CP_WAIT0();
        }
        __syncthreads();

        uint32_t bbase2 = sb + (ac ? SM_W1A : SM_XS) + boff_hcq;

        float c2[6][2][4];
#pragma unroll
        for (int p = 0; p < 6; p++)
#pragma unroll
            for (int j = 0; j < 2; j++)
#pragma unroll
                for (int e = 0; e < 4; e++) c2[p][j][e] = 0.f;

        uint32_t aC[4], bC[6][4];
        ldsm_x4(aC, abase2);
#pragma unroll
        for (int p = 0; p < 6; p++) ldsm_x4(bC[p], bbase2 + p * 16 * HK_STRIDE * 2);

#pragma unroll
        for (int kk = 0; kk < 16; kk++) {
            uint32_t aN[4], bN[6][4];
            if (kk < 15) {
                ldsm_x4(aN, abase2 + (kk + 1) * 32);
#pragma unroll
                for (int p = 0; p < 6; p++)
                    ldsm_x4(bN[p], bbase2 + p * 16 * HK_STRIDE * 2 + (kk + 1) * 32);
            }
#pragma unroll
            for (int p = 0; p < 6; p++) {
                mma_bf16(c2[p][0], aC, bC[p][0], bC[p][1]);
                mma_bf16(c2[p][1], aC, bC[p][2], bC[p][3]);
            }
            if (kk < 15) {
#pragma unroll
                for (int e = 0; e < 4; e++) aC[e] = aN[e];
#pragma unroll
                for (int p = 0; p < 6; p++)
#pragma unroll
                    for (int e = 0; e < 4; e++) bC[p][e] = bN[p][e];
            }
        }

        __syncthreads();   // all ldmatrix reads of this chunk's B-region done
        float* sdst = (float*)(smem + (ac ? SM_W1A : SM_XS));
        {
            float lamq = ((const float*)(smem + AXH_SCAL))[0];
            float onem = 1.f - lamq;
            float lqs = lamq * (1.f / 16.f);
            const float* rsp = (const float*)(smem + AXH_RS);
            const float* cq2_s = (const float*)(smem + AXH_CQ2);
            float rsa = (rsp[r0] + rsp[128 + r0]) * lqs;
            float rsb = (rsp[r0 + 8] + rsp[128 + r0 + 8]) * lqs;
#pragma unroll
            for (int p = 0; p < 6; p++) {
#pragma unroll
                for (int j = 0; j < 2; j++) {
                    int col = p * 16 + j * 8 + 2 * (lane & 3);
                    float cqa = cq2_s[ac * 96 + col], cqb = cq2_s[ac * 96 + col + 1];
                    *(float2*)(sdst + r0 * SS_STRIDE + col) = make_float2(
                        fmaf(onem, c2[p][j][0], rsa * cqa),
                        fmaf(onem, c2[p][j][1], rsa * cqb));
                    *(float2*)(sdst + (r0 + 8) * SS_STRIDE + col) = make_float2(
                        fmaf(onem, c2[p][j][2], rsb * cqa),
                        fmaf(onem, c2[p][j][3], rsb * cqb));
                }
            }
        }
    }
    __syncthreads();

    // ---- fused softmax partials: thread == a (192 active) -----------------
    if (tid < AA) {
        int a = tid;
        const float* ssm = (a < 96) ? (const float*)(smem + SM_XS)
                                    : (const float*)(smem + SM_W1A);
        int acol = (a < 96) ? a : (a - 96);
        float qbv = ((const float*)(smem + AXH_QB))[a];
        int tmax = TT - t0; if (tmax > 128) tmax = 128;

        float M = -1e30f;
        for (int t = 0; t < tmax; t++)
            M = fmaxf(M, ssm[t * SS_STRIDE + acol]);
        M += qbv;

        float Z = 0.f, S1 = 0.f, S2 = 0.f;
        const float* vp = ht + ((size_t)b * TT + t0) * CC + n * DD + a;
#pragma unroll 4
        for (int t = 0; t < tmax; t++) {
            float s = ssm[t * SS_STRIDE + acol] + qbv;
            float wv = __expf(s - M);
            float v = vp[(size_t)t * CC];
            Z += wv; S1 += wv * v; S2 += wv * v * v;
        }
        g_pp[((size_t)bn * 16 + blockIdx.x) * AA + a] = make_float4(M, Z, S1, S2);
    }
}

// ---------------- K4: merge 16 tile partials -> output ---------------------
__global__ __launch_bounds__(192) void k_pool_merge(float* __restrict__ out) {
    int bn = blockIdx.x;
    int b = bn >> 3, n = bn & 7;
    int a = threadIdx.x;

    const float4* pp = g_pp + (size_t)bn * 16 * AA + a;
    float M = -1e30f;
#pragma unroll
    for (int s = 0; s < 16; s++) M = fmaxf(M, pp[s * AA].x);
    float Zt = 0.f, S1t = 0.f, S2t = 0.f;
#pragma unroll
    for (int s = 0; s < 16; s++) {
        float4 p = pp[s * AA];
        float c = __expf(p.x - M);
        Zt += p.y * c; S1t += p.z * c; S2t += p.w * c;
    }
    float mu = S1t / Zt;
    float ex2 = S2t / Zt;
    float rh = sqrtf(fmaxf(ex2 - mu * mu, 1e-9f));
    out[(size_t)b * (2 * CC) + n * DD + a] = mu;
    out[(size_t)b * (2 * CC) + CC + n * DD + a] = rh;
}

// ---------------- launcher ------------------------------------------------
extern "C" void kernel_launch(void* const* d_in, const int* in_sizes, int n_in,
                              void* d_out, int out_size) {
    const float* ht       = (const float*)d_in[0];
    const float* k_proj_W = (const float*)d_in[1];
    const float* query    = (const float*)d_in[2];
    const float* uk_W     = (const float*)d_in[3];
    const float* u_q1W    = (const float*)d_in[4];
    const float* u_q2     = (const float*)d_in[5];
    const float* vhq      = (const float*)d_in[6];
    const float* vhk      = (const float*)d_in[7];
    const float* vcq      = (const float*)d_in[8];
    const float* vck      = (const float*)d_in[9];
    const float* k_proj_b = (const float*)d_in[10];
    const float* q_b      = (const float*)d_in[11];
    const float* u_q1b    = (const float*)d_in[12];
    const float* bnc_g    = (const float*)d_in[13];
    const float* bnc_b    = (const float*)d_in[14];
    const float* bnc_m    = (const float*)d_in[15];
    const float* bnc_v    = (const float*)d_in[16];
    const float* bnk_g    = (const float*)d_in[17];
    const float* bnk_b    = (const float*)d_in[18];
    const float* bnk_m    = (const float*)d_in[19];
    const float* bnk_v    = (const float*)d_in[20];
    float* out = (float*)d_out;

    static int smem_set = 0;
    if (!smem_set) {
        cudaFuncSetAttribute(k_scores_mma,
                             cudaFuncAttributeMaxDynamicSharedMemorySize, SMEM_SC);
        smem_set = 1;
    }

    // launch 1: fused front (stats + prepw + prepq + qdot/vcqsum)
    k_front<<<1216, 256>>>(ht, k_proj_W, query, vhq, vcq);

    // launch 2: ctx_a (hck, t1, ckdot partials)
    dim3 ga(8, NH);
    k_ctx_a<<<ga, 256>>>(uk_W, u_q1W, u_q1b, vck, bnc_g, bnc_b, bnc_m, bnc_v);

    // launch 3: ctx_b (cq2, vcqdot partials)
    dim3 gb(6, NH);
    k_ctx_b<<<gb, 256>>>(u_q2);

    // launch 4 (ncu-captured): fused scores kernel, pipelined inner loops
    dim3 gsc(16, BB * NH);
    k_scores_mma<<<gsc, 256, SMEM_SC>>>(ht, k_proj_b, bnk_g, bnk_b, bnk_m, bnk_v,
                                        vhk, q_b);

    // launch 5: merge
    k_pool_merge<<<BB * NH, AA>>>(out);
}